// round 8
// baseline (speedup 1.0000x reference)
#include <cuda_runtime.h>
#include <cstdint>

// Problem constants
#define B_       32
#define S_       160000
#define N_       320
#define H_       160
#define TAU_     257
#define FN_      1000
#define LAG_CUT_ 33
#define EPS_     1e-5f
#define OUT_TAUS (TAU_ - LAG_CUT_)   // 224
#define EXT_LEN  (N_ + TAU_ - 1)     // 576

#define WARPS_PER_BLOCK 4
#define SEG_PAD 600     // multiple of 4; slack for unconditional prefetch (max read 583)
#define CS_LEN  580     // >= 577

typedef unsigned long long u64;

__device__ __forceinline__ u64 fma2(u64 a, u64 b, u64 c) {
    u64 d;
    asm("fma.rn.f32x2 %0, %1, %2, %3;" : "=l"(d) : "l"(a), "l"(b), "l"(c));
    return d;
}
__device__ __forceinline__ float lo32(u64 v) { return __uint_as_float((unsigned)(v & 0xffffffffull)); }
__device__ __forceinline__ float hi32(u64 v) { return __uint_as_float((unsigned)(v >> 32)); }

__global__ void __launch_bounds__(WARPS_PER_BLOCK * 32, 6)
xcorr_kernel(const float* __restrict__ x, float* __restrict__ out) {
    __shared__ __align__(16) float s_seg[WARPS_PER_BLOCK][SEG_PAD];
    __shared__ __align__(16) float s_sh [WARPS_PER_BLOCK][SEG_PAD];
    __shared__ __align__(16) float s_cs [WARPS_PER_BLOCK][CS_LEN];

    const int warp = threadIdx.x >> 5;
    const int lane = threadIdx.x & 31;
    const int w = blockIdx.x * WARPS_PER_BLOCK + warp;   // window id [0, 32000)
    const int b = w / FN_;
    const int f = w - b * FN_;
    const float* xb = x + (size_t)b * S_;
    const int p  = f * H_;
    const int p2 = (f + 1 == FN_) ? 0 : (f + 1) * H_;    // wrap for f=999

    float* seg = s_seg[warp];
    float* ssh = s_sh [warp];
    float* cs  = s_cs [warp];

    // ---- Phase 1: stage extended window (batched LDG -> STS) ----
    {
        float v[18];
        #pragma unroll
        for (int i = 0; i < 18; i++) {
            const int j = lane + 32 * i;          // j < 576
            const int g = (j < N_) ? (p + j) : (p2 + (j - N_));
            v[i] = (g < S_) ? __ldg(xb + g) : 0.f;
        }
        #pragma unroll
        for (int i = 0; i < 18; i++) seg[lane + 32 * i] = v[i];
        // zero tail [576, 600)
        if (lane < SEG_PAD - EXT_LEN) seg[EXT_LEN + lane] = 0.f;
    }
    __syncwarp();

    // ---- shifted copy: ssh[j] = seg[j+1] (batched LDS -> STS) ----
    {
        float v[19];
        #pragma unroll
        for (int i = 0; i < 19; i++) {
            const int j = lane + 32 * i;
            v[i] = (j < SEG_PAD - 1) ? seg[j + 1] : 0.f;
        }
        #pragma unroll
        for (int i = 0; i < 19; i++) {
            const int j = lane + 32 * i;
            if (j < SEG_PAD) ssh[j] = v[i];
        }
    }

    // ---- Phase 2: warp prefix scan of seg^2 (576 values) ----
    {
        const int base = lane * 18;
        float sv[18];
        #pragma unroll
        for (int i = 0; i < 18; i++) sv[i] = seg[base + i];
        float partial = 0.f;
        #pragma unroll
        for (int i = 0; i < 18; i++) partial = fmaf(sv[i], sv[i], partial);
        float incl = partial;
        #pragma unroll
        for (int d = 1; d < 32; d <<= 1) {
            float t = __shfl_up_sync(0xffffffffu, incl, d);
            if (lane >= d) incl += t;
        }
        float run = incl - partial;
        #pragma unroll
        for (int i = 0; i < 18; i++) {
            run = fmaf(sv[i], sv[i], run);
            cs[base + i + 1] = run;
        }
        if (lane == 0) cs[0] = 0.f;
    }
    __syncwarp();

    // ---- Phase 3: tap-packed correlation. Lane owns 7 same-parity lags,
    //      full 320 taps, packed over tap pairs. lo+hi(acc) = num(tau). ----
    const int par = lane & 1;            // 1: odd lags, 0: even lags
    const int grp = lane >> 1;           // 0..15
    const int tau0 = (par ? 33 : 34) + 14 * grp;

    // window W[m] = pair (seg[tau0+2m], seg[tau0+2m+1])
    //   odd tau:  ssh u64 at float (tau0-1)   (even offset)
    //   even tau: seg u64 at float tau0       (even offset)
    const u64* warr = par ? (const u64*)(ssh + tau0 - 1)
                          : (const u64*)(seg + tau0);
    const u64* kptr = (const u64*)seg;   // K u64 idx q = pair (seg[2q], seg[2q+1])

    // preload window u64 idx 0..9
    u64 W[10];
    #pragma unroll
    for (int m = 0; m < 10; m++) W[m] = warr[m];

    u64 acc[7];
    #pragma unroll
    for (int c = 0; c < 7; c++) acc[c] = 0ull;

    // prefetch K for iter 0 (broadcast, 16B-aligned)
    ulonglong2 kA = *(const ulonglong2*)(kptr);
    ulonglong2 kB = *(const ulonglong2*)(kptr + 2);

    #pragma unroll
    for (int it = 0; it < 40; it++) {
        const int q = 4 * it;            // tap-pair base (tap n = 2q)
        const u64 k0 = kA.x, k1 = kA.y, k2 = kB.x, k3 = kB.y;

        // prefetch next-iter K and incoming window u64s (unconditional; pads cover)
        kA = *(const ulonglong2*)(kptr + q + 4);
        kB = *(const ulonglong2*)(kptr + q + 6);
        const u64 Wn0 = warr[q + 10];
        const u64 Wn1 = warr[q + 11];
        const u64 Wn2 = warr[q + 12];
        const u64 Wn3 = warr[q + 13];

        // tap-pair q+0..q+3: acc[c] += K[q+ql] * W[ql+c]
        #pragma unroll
        for (int c = 0; c < 7; c++) acc[c] = fma2(k0, W[c],     acc[c]);
        #pragma unroll
        for (int c = 0; c < 7; c++) acc[c] = fma2(k1, W[c + 1], acc[c]);
        #pragma unroll
        for (int c = 0; c < 7; c++) acc[c] = fma2(k2, W[c + 2], acc[c]);
        #pragma unroll
        for (int c = 0; c < 7; c++) acc[c] = fma2(k3, W[c + 3], acc[c]);

        // slide window by 4 u64 (renamed under full unroll)
        #pragma unroll
        for (int m = 0; m < 6; m++) W[m] = W[m + 4];
        W[6] = Wn0; W[7] = Wn1; W[8] = Wn2; W[9] = Wn3;
    }

    // ---- Epilogue: normalize + store (7 outputs per lane, stride 2) ----
    const float e0 = cs[N_];
    float* ow = out + (size_t)w * OUT_TAUS + (tau0 - LAG_CUT_);
    #pragma unroll
    for (int c = 0; c < 7; c++) {
        const int tau = tau0 + 2 * c;
        const float num = lo32(acc[c]) + hi32(acc[c]);
        const float den = e0 + (cs[tau + N_] - cs[tau]) + EPS_;
        ow[2 * c] = __fdividef(2.f * num, den);
    }
}

extern "C" void kernel_launch(void* const* d_in, const int* in_sizes, int n_in,
                              void* d_out, int out_size) {
    const float* x = (const float*)d_in[0];
    float* out = (float*)d_out;
    const int n_windows = B_ * FN_;                       // 32000
    dim3 grid(n_windows / WARPS_PER_BLOCK);               // 8000 blocks
    xcorr_kernel<<<grid, WARPS_PER_BLOCK * 32>>>(x, out);
}

// round 10
// speedup vs baseline: 1.1351x; 1.1351x over previous
#include <cuda_runtime.h>
#include <cstdint>

// Problem constants
#define B_       32
#define S_       160000
#define N_       320
#define H_       160
#define TAU_     257
#define FN_      1000
#define LAG_CUT_ 33
#define EPS_     1e-5f
#define OUT_TAUS (TAU_ - LAG_CUT_)   // 224
#define EXT_LEN  (N_ + TAU_ - 1)     // 576

#define WARPS_PER_BLOCK 4
#define XS_LEN  896     // union: window w uses xs[160w .. 160w+416)
#define CS_PAD  900     // needs [0, 896]
#define SEG_LEN 600     // per-warp window buffer (max mainloop read 583)
#define KD_LEN  336     // 4 tap-groups of 80 u64 + 4-u64 pad each
#define SPCS    580

typedef unsigned long long u64;

__device__ __forceinline__ u64 fma2(u64 a, u64 b, u64 c) {
    u64 d;
    asm("fma.rn.f32x2 %0, %1, %2, %3;" : "=l"(d) : "l"(a), "l"(b), "l"(c));
    return d;
}
__device__ __forceinline__ u64 add2(u64 a, u64 b) {
    u64 d;
    asm("add.rn.f32x2 %0, %1, %2;" : "=l"(d) : "l"(a), "l"(b));
    return d;
}
__device__ __forceinline__ float lo32(u64 v) { return __uint_as_float((unsigned)(v & 0xffffffffull)); }
__device__ __forceinline__ float hi32(u64 v) { return __uint_as_float((unsigned)(v >> 32)); }

__global__ void __launch_bounds__(WARPS_PER_BLOCK * 32, 4)
xcorr_kernel(const float* __restrict__ x, float* __restrict__ out) {
    __shared__ __align__(16) float  s_xs  [XS_LEN];
    __shared__ __align__(16) float  s_CS  [CS_PAD];
    __shared__ __align__(16) float  s_seg [WARPS_PER_BLOCK][SEG_LEN];
    __shared__ __align__(16) float  s_ssh [WARPS_PER_BLOCK][SEG_LEN];
    __shared__ __align__(16) float2 s_kd  [WARPS_PER_BLOCK][KD_LEN];
    __shared__ __align__(16) float  s_wtot[WARPS_PER_BLOCK];
    // private buffers for the f=999 wraparound window (1 block in 250)
    __shared__ __align__(16) float  s_pseg[SEG_LEN];
    __shared__ __align__(16) float  s_psh [SEG_LEN];
    __shared__ __align__(16) float  s_pcs [SPCS];

    const int tid  = threadIdx.x;
    const int warp = tid >> 5;
    const int lane = tid & 31;
    const int w0 = blockIdx.x * WARPS_PER_BLOCK;         // first window of block
    const int b  = w0 / FN_;
    const int f0 = w0 - b * FN_;                          // multiple of 4; no batch straddle
    const float* xb = x + (size_t)b * S_;
    const int p0 = f0 * H_;
    const bool priv = (f0 == FN_ - 4) && (warp == 3);     // f=999 wraparound window

    // ---- Phase 1a: stage union xs[0,896) = xb[p0 + j] (batched, exact fit) ----
    {
        float v[7];
        #pragma unroll
        for (int i = 0; i < 7; i++) {
            const int g = p0 + tid + 128 * i;
            v[i] = (g < S_) ? __ldg(xb + g) : 0.f;
        }
        #pragma unroll
        for (int i = 0; i < 7; i++) s_xs[tid + 128 * i] = v[i];
    }

    // ---- Phase 1b (rare): private staging + scan for the wrap window f=999 ----
    if (priv) {
        const int p = (FN_ - 1) * H_;                     // 159840
        float v[18];
        #pragma unroll
        for (int i = 0; i < 18; i++) {
            const int j = lane + 32 * i;                  // j < 576
            const int g = (j < N_) ? (p + j) : (j - N_);  // tail wraps to frame 0
            v[i] = (g < S_) ? __ldg(xb + g) : 0.f;
        }
        #pragma unroll
        for (int i = 0; i < 18; i++) s_pseg[lane + 32 * i] = v[i];
        if (lane < SEG_LEN - EXT_LEN) s_pseg[EXT_LEN + lane] = 0.f;
        __syncwarp();
        float sv[19];
        #pragma unroll
        for (int i = 0; i < 19; i++) {
            const int j = lane + 32 * i;
            sv[i] = (j < SEG_LEN - 1) ? s_pseg[j + 1] : 0.f;
        }
        #pragma unroll
        for (int i = 0; i < 19; i++) {
            const int j = lane + 32 * i;
            if (j < SEG_LEN) s_psh[j] = sv[i];
        }
        {
            const int base = lane * 18;
            float e[18];
            #pragma unroll
            for (int i = 0; i < 18; i++) e[i] = s_pseg[base + i];
            float partial = 0.f;
            #pragma unroll
            for (int i = 0; i < 18; i++) partial = fmaf(e[i], e[i], partial);
            float incl = partial;
            #pragma unroll
            for (int d = 1; d < 32; d <<= 1) {
                float t2 = __shfl_up_sync(0xffffffffu, incl, d);
                if (lane >= d) incl += t2;
            }
            float run = incl - partial;
            #pragma unroll
            for (int i = 0; i < 18; i++) {
                run = fmaf(e[i], e[i], run);
                s_pcs[base + i + 1] = run;
            }
            if (lane == 0) s_pcs[0] = 0.f;
        }
    }
    __syncthreads();

    // ---- Phase 2a: block scan of xs^2 -> CSg[0..896] (7 vals/thread, exact) ----
    {
        const int base = tid * 7;
        float e[7];
        #pragma unroll
        for (int i = 0; i < 7; i++) e[i] = s_xs[base + i];
        float partial = 0.f;
        #pragma unroll
        for (int i = 0; i < 7; i++) partial = fmaf(e[i], e[i], partial);
        float incl = partial;
        #pragma unroll
        for (int d = 1; d < 32; d <<= 1) {
            float t2 = __shfl_up_sync(0xffffffffu, incl, d);
            if (lane >= d) incl += t2;
        }
        if (lane == 31) s_wtot[warp] = incl;
        __syncthreads();
        float woff = 0.f;
        #pragma unroll
        for (int ww = 0; ww < WARPS_PER_BLOCK; ww++)
            if (ww < warp) woff += s_wtot[ww];
        float run = woff + incl - partial;
        #pragma unroll
        for (int i = 0; i < 7; i++) {
            run = fmaf(e[i], e[i], run);
            s_CS[base + i + 1] = run;
        }
        if (tid == 0) s_CS[0] = 0.f;
    }

    // ---- Phase 2b: per-warp seg/ssh from xs with the j=320 seam ----
    // ext[j] = xs[o + j] (j<320), xs[o + j - 160] (j>=320)
    const int o = H_ * warp;
    float* seg = s_seg[warp];
    float* ssh = s_ssh[warp];
    if (!priv) {
        float va[18], vb[18];
        #pragma unroll
        for (int i = 0; i < 18; i++) {
            const int j = lane + 32 * i;                  // j < 576
            const int jj  = (j     < N_) ? j     : (j - H_);
            const int j2  = j + 1;
            const int jj2 = (j2    < N_) ? j2    : (j2 - H_);
            va[i] = s_xs[o + jj];
            vb[i] = (j2 < EXT_LEN) ? s_xs[o + jj2] : 0.f;
        }
        #pragma unroll
        for (int i = 0; i < 18; i++) {
            const int j = lane + 32 * i;
            seg[j] = va[i];
            ssh[j] = vb[i];
        }
        if (lane < SEG_LEN - EXT_LEN) {
            seg[EXT_LEN + lane] = 0.f;
            ssh[EXT_LEN + lane] = 0.f;
        }
    }
    __syncwarp();

    // ---- Phase 2c: per-warp kd (duplicated-k pairs, 4 groups + zeroed pads) ----
    const float* segp = priv ? s_pseg : seg;
    const float* sshp = priv ? s_psh  : ssh;
    float2* kd = s_kd[warp];
    {
        float v[10];
        #pragma unroll
        for (int i = 0; i < 10; i++) v[i] = segp[lane + 32 * i];  // taps 0..319
        #pragma unroll
        for (int i = 0; i < 10; i++) {
            const int n = lane + 32 * i;
            const int grp = n / 80;
            kd[n + 4 * grp] = make_float2(v[i], v[i]);
        }
        if (lane < 16) {
            const int grp = lane >> 2;
            kd[80 + 84 * grp + (lane & 3)] = make_float2(0.f, 0.f);
        }
    }
    __syncthreads();   // CSg visible block-wide for epilogue

    // ---- Phase 3: 8 lag-groups x 4 tap-groups; 28 lags x 80 taps per lane ----
    const int g = lane & 7;
    const int h = lane >> 3;
    const int t = LAG_CUT_ + 28 * g;
    const int start = (t - 1) + 80 * h;                   // 16B-aligned

    const float* sp = segp + start;
    const float* bp = sshp + start;
    const float2* kp = kd + 84 * h;

    ulonglong2 A[8], Bv[8];
    #pragma unroll
    for (int c = 0; c < 7; c++) {
        A[c]  = *(const ulonglong2*)(sp + 4 * c);
        Bv[c] = *(const ulonglong2*)(bp + 4 * c);
    }

    u64 acc[14];
    #pragma unroll
    for (int j = 0; j < 14; j++) acc[j] = 0ull;

    ulonglong2 An = *(const ulonglong2*)(sp + 28);
    ulonglong2 Bn = *(const ulonglong2*)(bp + 28);
    ulonglong2 k0 = *(const ulonglong2*)(kp);
    ulonglong2 k1 = *(const ulonglong2*)(kp + 2);

    #pragma unroll
    for (int it = 0; it < 20; it++) {
        A[7]  = An;
        Bv[7] = Bn;
        const ulonglong2 kq0 = k0;
        const ulonglong2 kq1 = k1;

        An = *(const ulonglong2*)(sp + 4 * it + 32);
        Bn = *(const ulonglong2*)(bp + 4 * it + 32);
        k0 = *(const ulonglong2*)(kp + 4 * it + 4);
        k1 = *(const ulonglong2*)(kp + 4 * it + 6);

        #pragma unroll
        for (int j = 0; j < 14; j++)
            acc[j] = fma2(kq0.x, (j & 1) ? Bv[j >> 1].y : Bv[j >> 1].x, acc[j]);
        #pragma unroll
        for (int j = 0; j < 14; j++)
            acc[j] = fma2(kq0.y, (j & 1) ? A[(j + 1) >> 1].x : A[(j + 1) >> 1].y, acc[j]);
        #pragma unroll
        for (int j = 0; j < 14; j++)
            acc[j] = fma2(kq1.x, (j & 1) ? Bv[(j + 1) >> 1].x : Bv[(j + 1) >> 1].y, acc[j]);
        #pragma unroll
        for (int j = 0; j < 14; j++)
            acc[j] = fma2(kq1.y, (j & 1) ? A[(j + 2) >> 1].y : A[(j + 2) >> 1].x, acc[j]);

        #pragma unroll
        for (int c = 0; c < 7; c++) { A[c] = A[c + 1]; Bv[c] = Bv[c + 1]; }
    }

    // ---- reduce partial sums across the 4 tap-groups (lane bits 3,4) ----
    #pragma unroll
    for (int j = 0; j < 14; j++) {
        u64 v = acc[j];
        v = add2(v, __shfl_xor_sync(0xffffffffu, v, 8));
        v = add2(v, __shfl_xor_sync(0xffffffffu, v, 16));
        acc[j] = v;
    }

    // ---- Epilogue. den(tau) = A0 - P[tau] + Q[tau]:
    //  non-priv (seam): e_tau = (C[320]-C[tau]) + (C[tau+160]-C[160]),
    //    A0 = 2C[320] - C[0] - C[160] + EPS,  P = C, Q = C+160
    //  priv (true window scan): A0 = pcs[320] - pcs[0] + EPS, P = pcs, Q = pcs+320
    const float* P;
    const float* Q;
    float A0;
    if (priv) {
        P = s_pcs; Q = s_pcs + N_;
        A0 = s_pcs[N_] - s_pcs[0] + EPS_;
    } else {
        const float* C = s_CS + o;
        P = C; Q = C + H_;
        A0 = 2.f * C[N_] - C[0] - C[H_] + EPS_;
    }
    float* ow = out + (size_t)(w0 + warp) * OUT_TAUS + 28 * g;
    #pragma unroll
    for (int j0 = 0; j0 < 4; j0++) {
        int j = h + 4 * j0;
        if (j < 14) {
            int tau = t + 2 * j;
            float n0 = lo32(acc[j]);
            float n1 = hi32(acc[j]);
            float d0 = A0 - P[tau]     + Q[tau];
            float d1 = A0 - P[tau + 1] + Q[tau + 1];
            float2 r = make_float2(__fdividef(2.f * n0, d0),
                                   __fdividef(2.f * n1, d1));
            *(float2*)(ow + 2 * j) = r;
        }
    }
}

extern "C" void kernel_launch(void* const* d_in, const int* in_sizes, int n_in,
                              void* d_out, int out_size) {
    const float* x = (const float*)d_in[0];
    float* out = (float*)d_out;
    const int n_windows = B_ * FN_;                       // 32000
    dim3 grid(n_windows / WARPS_PER_BLOCK);               // 8000 blocks
    xcorr_kernel<<<grid, WARPS_PER_BLOCK * 32>>>(x, out);
}